// round 11
// baseline (speedup 1.0000x reference)
#include <cuda_runtime.h>
#include <cstddef>

typedef unsigned long long ull;

#define Nn   512
#define IND  256
#define HIDD 256
#define AH   128
#define OUTD 256
#define WELD 262   // IN_DIM + 6
#define SCALE 0.08838834764831845f

// ---------------- scratch ----------------
__device__ float g_F[Nn * HIDD];
__device__ float g_qk[Nn * HIDD];
__device__ float g_Wqk[IND * HIDD];
__device__ float g_Gt[OUTD * HIDD];
__device__ float g_bqk[HIDD];
__device__ float g_bo2[OUTD];
__device__ float g_o1[Nn * OUTD];
__device__ float g_wp[2 * Nn * HIDD];
__device__ float g_lp[2 * Nn];

// ---------------- f32x2 helpers ----------------
__device__ __forceinline__ ull pack2(float lo, float hi) {
    ull r; asm("mov.b64 %0,{%1,%2};" : "=l"(r) : "f"(lo), "f"(hi)); return r;
}
__device__ __forceinline__ float2 unp2(ull x) {
    float2 f; asm("mov.b64 {%0,%1},%2;" : "=f"(f.x), "=f"(f.y) : "l"(x)); return f;
}
__device__ __forceinline__ ull fma2(ull a, ull b, ull c) {
    ull d; asm("fma.rn.f32x2 %0,%1,%2,%3;" : "=l"(d) : "l"(a), "l"(b), "l"(c)); return d;
}
__device__ __forceinline__ ull relu2(ull x) {
    ull r;
    asm("{.reg .f32 lo,hi;\n\t"
        "mov.b64 {lo,hi},%1;\n\t"
        "max.f32 lo,lo,0f00000000;\n\t"
        "max.f32 hi,hi,0f00000000;\n\t"
        "mov.b64 %0,{lo,hi};}" : "=l"(r) : "l"(x));
    return r;
}

// ============ launch A: weight-only precomputes =============================
// bid<64 : Wqk[f,h] = SCALE * sum_a Wq[a,f]*Wk[a,h]      (K=128)
// bid<128: Gt[n,h]  = sum_d Wo[n,256+d]*Wv[d,h]          (K=256)
// bid=128: bo2 = bo + Wo2@bv ;  bid=129: bqk = SCALE*(bq@Wk)
__global__ __launch_bounds__(256) void preA_k(
    const float* __restrict__ Wq, const float* __restrict__ Wk,
    const float* __restrict__ Wo, const float* __restrict__ Wv,
    const float* __restrict__ bq, const float* __restrict__ bv,
    const float* __restrict__ bo,
    float* __restrict__ Wqk, float* __restrict__ Gt,
    float* __restrict__ bo2, float* __restrict__ bqk)
{
    const int bid = blockIdx.x;
    const int t = threadIdx.x;

    if (bid >= 128) {
        if (bid == 128) {                       // bo2
            float acc = bo[t];
            const float* arow = Wo + (size_t)t * 512 + 256;
#pragma unroll 8
            for (int d = 0; d < 256; d++) acc += bv[d] * arow[d];
            bo2[t] = acc;
        } else {                                // bqk
            float acc = 0.f;
#pragma unroll 8
            for (int a = 0; a < 128; a++) acc += bq[a] * Wk[(size_t)a * HIDD + t];
            bqk[t] = acc * SCALE;
        }
        return;
    }

    __shared__ float As[2][32][34];
    __shared__ float Bs[2][32][34];
    const int tx = t & 15, ty = t >> 4;
    const bool isW = bid < 64;
    const int x = isW ? bid : bid - 64;
    const int mb = (x >> 3) * 32, nb = (x & 7) * 32;
    const int steps = isW ? 4 : 8;

    float ra[4], rb[4];
#pragma unroll
    for (int r = 0; r < 4; r++) {
        int idx = t + r * 256;
        if (isW) {
            int kq = idx >> 5, pq = idx & 31;
            ra[r] = Wq[(size_t)kq * IND + mb + pq];
            rb[r] = Wk[(size_t)kq * HIDD + nb + pq];
        } else {
            int p = idx >> 5, s = idx & 31;
            ra[r] = Wo[(size_t)(mb + p) * 512 + 256 + s];
            rb[r] = Wv[(size_t)p * HIDD + nb + s];
        }
    }
#pragma unroll
    for (int r = 0; r < 4; r++) {
        int idx = t + r * 256;
        if (isW) {
            int kq = idx >> 5, pq = idx & 31;
            As[0][kq][pq] = ra[r];
            Bs[0][kq][pq] = rb[r];
        } else {
            int p = idx >> 5, s = idx & 31;
            As[0][s][p] = ra[r];
            Bs[0][p][s] = rb[r];
        }
    }
    __syncthreads();

    float a00 = 0.f, a01 = 0.f, a10 = 0.f, a11 = 0.f;
    for (int step = 0; step < steps; step++) {
        int cur = step & 1;
        if (step < steps - 1) {
            int k0 = (step + 1) * 32;
#pragma unroll
            for (int r = 0; r < 4; r++) {
                int idx = t + r * 256;
                if (isW) {
                    int kq = idx >> 5, pq = idx & 31;
                    ra[r] = Wq[(size_t)(k0 + kq) * IND + mb + pq];
                    rb[r] = Wk[(size_t)(k0 + kq) * HIDD + nb + pq];
                } else {
                    int p = idx >> 5, s = idx & 31;
                    ra[r] = Wo[(size_t)(mb + p) * 512 + 256 + k0 + s];
                    rb[r] = Wv[(size_t)(k0 + p) * HIDD + nb + s];
                }
            }
        }
#pragma unroll
        for (int kk = 0; kk < 32; kk++) {
            float2 av = *(const float2*)&As[cur][kk][ty * 2];
            float2 bv2 = *(const float2*)&Bs[cur][kk][tx * 2];
            a00 = fmaf(av.x, bv2.x, a00);
            a01 = fmaf(av.x, bv2.y, a01);
            a10 = fmaf(av.y, bv2.x, a10);
            a11 = fmaf(av.y, bv2.y, a11);
        }
        if (step < steps - 1) {
            __syncthreads();
            int nxt = cur ^ 1;
#pragma unroll
            for (int r = 0; r < 4; r++) {
                int idx = t + r * 256;
                if (isW) {
                    int kq = idx >> 5, pq = idx & 31;
                    As[nxt][kq][pq] = ra[r];
                    Bs[nxt][kq][pq] = rb[r];
                } else {
                    int p = idx >> 5, s = idx & 31;
                    As[nxt][s][p] = ra[r];
                    Bs[nxt][p][s] = rb[r];
                }
            }
            __syncthreads();
        }
    }

    int m = mb + ty * 2, n = nb + tx * 2;
    if (isW) {
        Wqk[(size_t)m * HIDD + n]           = a00 * SCALE;
        Wqk[(size_t)m * HIDD + n + 1]       = a01 * SCALE;
        Wqk[(size_t)(m + 1) * HIDD + n]     = a10 * SCALE;
        Wqk[(size_t)(m + 1) * HIDD + n + 1] = a11 * SCALE;
    } else {
        Gt[(size_t)m * HIDD + n]           = a00;
        Gt[(size_t)m * HIDD + n + 1]       = a01;
        Gt[(size_t)(m + 1) * HIDD + n]     = a10;
        Gt[(size_t)(m + 1) * HIDD + n + 1] = a11;
    }
}

// ============ launch B: all app-contractions (K=256) ========================
// bid<128 : F   = app@We6^T + be
// bid<256 : qk  = app@Wqk + bqk          (Wqk pre-scaled)
// else    : out1= app@Wo1^T              (bias deferred to post)
__global__ __launch_bounds__(256) void preB_k(
    const float* __restrict__ app,
    const float* __restrict__ We6,
    const float* __restrict__ Wqk,
    const float* __restrict__ Wo,
    const float* __restrict__ be,
    const float* __restrict__ bqk,
    float* __restrict__ F,
    float* __restrict__ qk,
    float* __restrict__ o1)
{
    __shared__ float As[2][32][34];
    __shared__ float Bs[2][32][34];
    const int t = threadIdx.x;
    const int tx = t & 15, ty = t >> 4;
    const int bid = blockIdx.x;
    const int mode = bid >> 7;                   // 0:F 1:qk 2:o1
    const int x = bid & 127;
    const int mb = (x >> 3) * 32, nb = (x & 7) * 32;

    float ra[4], rb[4];
#pragma unroll
    for (int r = 0; r < 4; r++) {
        int idx = t + r * 256, p = idx >> 5, s = idx & 31;
        ra[r] = app[(size_t)(mb + p) * IND + s];
        rb[r] = (mode == 0) ? We6[(size_t)(nb + p) * WELD + s]
              : (mode == 1) ? Wqk[(size_t)p * HIDD + nb + s]
                            : Wo[(size_t)(nb + p) * 512 + s];
    }
#pragma unroll
    for (int r = 0; r < 4; r++) {
        int idx = t + r * 256, p = idx >> 5, s = idx & 31;
        As[0][s][p] = ra[r];
        if (mode == 1) Bs[0][p][s] = rb[r]; else Bs[0][s][p] = rb[r];
    }
    __syncthreads();

    float a00 = 0.f, a01 = 0.f, a10 = 0.f, a11 = 0.f;
    for (int step = 0; step < 8; step++) {
        int cur = step & 1;
        if (step < 7) {
            int k0 = (step + 1) * 32;
#pragma unroll
            for (int r = 0; r < 4; r++) {
                int idx = t + r * 256, p = idx >> 5, s = idx & 31;
                ra[r] = app[(size_t)(mb + p) * IND + k0 + s];
                rb[r] = (mode == 0) ? We6[(size_t)(nb + p) * WELD + k0 + s]
                      : (mode == 1) ? Wqk[(size_t)(k0 + p) * HIDD + nb + s]
                                    : Wo[(size_t)(nb + p) * 512 + k0 + s];
            }
        }
#pragma unroll
        for (int kk = 0; kk < 32; kk++) {
            float2 av = *(const float2*)&As[cur][kk][ty * 2];
            float2 bv2 = *(const float2*)&Bs[cur][kk][tx * 2];
            a00 = fmaf(av.x, bv2.x, a00);
            a01 = fmaf(av.x, bv2.y, a01);
            a10 = fmaf(av.y, bv2.x, a10);
            a11 = fmaf(av.y, bv2.y, a11);
        }
        if (step < 7) {
            __syncthreads();
            int nxt = cur ^ 1;
#pragma unroll
            for (int r = 0; r < 4; r++) {
                int idx = t + r * 256, p = idx >> 5, s = idx & 31;
                As[nxt][s][p] = ra[r];
                if (mode == 1) Bs[nxt][p][s] = rb[r]; else Bs[nxt][s][p] = rb[r];
            }
            __syncthreads();
        }
    }

    int m = mb + ty * 2, n = nb + tx * 2;
    float* C  = (mode == 0) ? F : (mode == 1) ? qk : o1;
    const float* bias = (mode == 0) ? be : (mode == 1) ? bqk : nullptr;
    float b0 = bias ? bias[n] : 0.f;
    float b1 = bias ? bias[n + 1] : 0.f;
    C[(size_t)m * HIDD + n]           = a00 + b0;
    C[(size_t)m * HIDD + n + 1]       = a01 + b1;
    C[(size_t)(m + 1) * HIDD + n]     = a10 + b0;
    C[(size_t)(m + 1) * HIDD + n + 1] = a11 + b1;
}

// ============ fused attention middle ========================================
// grid 512 = (256 i-pairs) x (2 j-halves); 128 threads (4 warps).
// Warp w: j = j0 + tau*4 + w, tau 0..63. Lane l owns h = 8l..8l+7.
// Writes UNNORMALIZED partials wp[jh] and row sums lp[jh]; post normalizes.
__global__ __launch_bounds__(128) void fused_k(
    const float* __restrict__ edges,
    const float* __restrict__ We,
    const float* __restrict__ Fm,
    const float* __restrict__ qkm,
    float* __restrict__ wp,
    float* __restrict__ lp)
{
    __shared__ __align__(16) float e_s[2 * 256 * 6];   // 12KB
    __shared__ __align__(16) ull waccs[4 * 32 * 9];    // 9216B
    __shared__ float wl[8];

    const int t = threadIdx.x, l = t & 31, w = t >> 5;
    const int bx = blockIdx.x;
    const int ib = (bx >> 1) * 2, jh = bx & 1, j0 = jh * 256;

    {   // stage edges: rows ib, ib+1, cols j0..j0+255 (float4, coalesced)
        const float4* s0 = (const float4*)(edges + ((size_t)ib * Nn + j0) * 6);
        const float4* s1 = (const float4*)(edges + ((size_t)(ib + 1) * Nn + j0) * 6);
        float4* d0 = (float4*)e_s;
        float4* d1 = (float4*)(e_s + 1536);
#pragma unroll
        for (int r = 0; r < 3; r++) {
            int idx = t + r * 128;
            d0[idx] = s0[idx];
            d1[idx] = s1[idx];
        }
    }

    ull W2[4][6];
#pragma unroll
    for (int k = 0; k < 4; k++) {
        int h0 = 8 * l + 2 * k;
#pragma unroll
        for (int c = 0; c < 6; c++)
            W2[k][c] = pack2(We[(size_t)h0 * WELD + c],
                             We[(size_t)(h0 + 1) * WELD + c]);
    }
    ull qk2[2][4];
#pragma unroll
    for (int i = 0; i < 2; i++) {
        const float* qa = qkm + (size_t)(ib + i) * HIDD + 8 * l;
        float4 v0 = *(const float4*)qa;
        float4 v1 = *(const float4*)(qa + 4);
        qk2[i][0] = pack2(v0.x, v0.y); qk2[i][1] = pack2(v0.z, v0.w);
        qk2[i][2] = pack2(v1.x, v1.y); qk2[i][3] = pack2(v1.z, v1.w);
    }
    __syncthreads();

    ull z = pack2(0.f, 0.f);
    ull acc[2][4] = {{z, z, z, z}, {z, z, z, z}};
    float lw0 = 0.f, lw1 = 0.f;

    ull Fc[4], Fn[4];
    {
        const float* fp = Fm + (size_t)(j0 + w) * HIDD + 8 * l;
        float4 v0 = *(const float4*)fp;
        float4 v1 = *(const float4*)(fp + 4);
        Fc[0] = pack2(v0.x, v0.y); Fc[1] = pack2(v0.z, v0.w);
        Fc[2] = pack2(v1.x, v1.y); Fc[3] = pack2(v1.z, v1.w);
    }

    for (int tau = 0; tau < 64; tau++) {
        const int jl = tau * 4 + w;
        const int jj = j0 + jl;
        if (tau < 63) {
            const float* fp = Fm + (size_t)(jj + 4) * HIDD + 8 * l;
            float4 v0 = *(const float4*)fp;
            float4 v1 = *(const float4*)(fp + 4);
            Fn[0] = pack2(v0.x, v0.y); Fn[1] = pack2(v0.z, v0.w);
            Fn[2] = pack2(v1.x, v1.y); Fn[3] = pack2(v1.z, v1.w);
        }
#pragma unroll
        for (int i = 0; i < 2; i++) {
            const float* ep = e_s + (size_t)(i * 256 + jl) * 6;  // broadcast
            ull e0 = pack2(ep[0], ep[0]);
            ull e1 = pack2(ep[1], ep[1]);
            ull e2 = pack2(ep[2], ep[2]);
            ull e3 = pack2(ep[3], ep[3]);
            ull e4 = pack2(ep[4], ep[4]);
            ull e5 = pack2(ep[5], ep[5]);
            ull g[4];
#pragma unroll
            for (int k = 0; k < 4; k++) {
                ull gg = fma2(e0, W2[k][0], Fc[k]);
                gg = fma2(e1, W2[k][1], gg);
                gg = fma2(e2, W2[k][2], gg);
                gg = fma2(e3, W2[k][3], gg);
                gg = fma2(e4, W2[k][4], gg);
                gg = fma2(e5, W2[k][5], gg);
                g[k] = relu2(gg);
            }
            ull sd = fma2(qk2[i][0], g[0], z);
            sd = fma2(qk2[i][1], g[1], sd);
            sd = fma2(qk2[i][2], g[2], sd);
            sd = fma2(qk2[i][3], g[3], sd);
            float2 sv = unp2(sd);
            float s = sv.x + sv.y;
#pragma unroll
            for (int o = 16; o; o >>= 1)
                s += __shfl_xor_sync(0xffffffffu, s, o);
            float p = (jj == ib + i) ? 0.f : __expf(s);
            if (i == 0) lw0 += p; else lw1 += p;
            ull p2 = pack2(p, p);
#pragma unroll
            for (int k = 0; k < 4; k++)
                acc[i][k] = fma2(p2, g[k], acc[i][k]);
        }
#pragma unroll
        for (int k = 0; k < 4; k++) Fc[k] = Fn[k];
    }

    ull* wb = waccs + (w * 32 + l) * 9;
#pragma unroll
    for (int k = 0; k < 4; k++) { wb[k] = acc[0][k]; wb[4 + k] = acc[1][k]; }
    if (l == 0) { wl[w * 2] = lw0; wl[w * 2 + 1] = lw1; }
    __syncthreads();

    float* wpd = wp + (size_t)jh * (Nn * HIDD);
    for (int idx = t; idx < 256; idx += 128) {
        int i = idx >> 7, hp = idx & 127;
        int lo = hp >> 2, ko = hp & 3;
        float sx = 0.f, sy = 0.f, li = 0.f;
#pragma unroll
        for (int ww = 0; ww < 4; ww++) {
            float2 v = unp2(waccs[(ww * 32 + lo) * 9 + i * 4 + ko]);
            sx += v.x; sy += v.y;
            li += wl[ww * 2 + i];
        }
        *(float2*)(wpd + (size_t)(ib + i) * HIDD + 2 * hp) =
            make_float2(sx, sy);
        if (hp == 0) lp[jh * Nn + ib + i] = li;
    }
}

// ============ post: out = relu(out1 + wcomb@Gt^T + bo2), K=256 ==============
// wcomb[m,k] = (wp0[m,k] + wp1[m,k]) / (lp0[m] + lp1[m])  (built at staging)
__global__ __launch_bounds__(256) void post_k(
    const float* __restrict__ wp,
    const float* __restrict__ lp,
    const float* __restrict__ Gt,
    const float* __restrict__ o1,
    const float* __restrict__ bo2,
    float* __restrict__ out)
{
    __shared__ float As[2][32][34];
    __shared__ float Bs[2][32][34];
    __shared__ float linv[32];
    const int t = threadIdx.x;
    const int tx = t & 15, ty = t >> 4;
    const int mb = (blockIdx.x >> 3) * 32, nb = (blockIdx.x & 7) * 32;

    if (t < 32)
        linv[t] = 1.f / (lp[mb + t] + lp[Nn + mb + t]);
    __syncthreads();

    float ra[4], rb[4];
#pragma unroll
    for (int r = 0; r < 4; r++) {
        int idx = t + r * 256, p = idx >> 5, s = idx & 31;
        ra[r] = (wp[(size_t)(mb + p) * HIDD + s] +
                 wp[(size_t)(Nn + mb + p) * HIDD + s]) * linv[p];
        rb[r] = Gt[(size_t)(nb + p) * HIDD + s];
    }
#pragma unroll
    for (int r = 0; r < 4; r++) {
        int idx = t + r * 256, p = idx >> 5, s = idx & 31;
        As[0][s][p] = ra[r];
        Bs[0][s][p] = rb[r];
    }
    __syncthreads();

    float a00 = 0.f, a01 = 0.f, a10 = 0.f, a11 = 0.f;
    for (int step = 0; step < 8; step++) {
        int cur = step & 1;
        if (step < 7) {
            int k0 = (step + 1) * 32;
#pragma unroll
            for (int r = 0; r < 4; r++) {
                int idx = t + r * 256, p = idx >> 5, s = idx & 31;
                ra[r] = (wp[(size_t)(mb + p) * HIDD + k0 + s] +
                         wp[(size_t)(Nn + mb + p) * HIDD + k0 + s]) * linv[p];
                rb[r] = Gt[(size_t)(nb + p) * HIDD + k0 + s];
            }
        }
#pragma unroll
        for (int kk = 0; kk < 32; kk++) {
            float2 av = *(const float2*)&As[cur][kk][ty * 2];
            float2 bv2 = *(const float2*)&Bs[cur][kk][tx * 2];
            a00 = fmaf(av.x, bv2.x, a00);
            a01 = fmaf(av.x, bv2.y, a01);
            a10 = fmaf(av.y, bv2.x, a10);
            a11 = fmaf(av.y, bv2.y, a11);
        }
        if (step < 7) {
            __syncthreads();
            int nxt = cur ^ 1;
#pragma unroll
            for (int r = 0; r < 4; r++) {
                int idx = t + r * 256, p = idx >> 5, s = idx & 31;
                As[nxt][s][p] = ra[r];
                Bs[nxt][s][p] = rb[r];
            }
            __syncthreads();
        }
    }

    int m = mb + ty * 2, n = nb + tx * 2;
    float b0 = bo2[n], b1 = bo2[n + 1];
    out[(size_t)m * OUTD + n] =
        fmaxf(a00 + o1[(size_t)m * OUTD + n] + b0, 0.f);
    out[(size_t)m * OUTD + n + 1] =
        fmaxf(a01 + o1[(size_t)m * OUTD + n + 1] + b1, 0.f);
    out[(size_t)(m + 1) * OUTD + n] =
        fmaxf(a10 + o1[(size_t)(m + 1) * OUTD + n] + b0, 0.f);
    out[(size_t)(m + 1) * OUTD + n + 1] =
        fmaxf(a11 + o1[(size_t)(m + 1) * OUTD + n + 1] + b1, 0.f);
}

// ---------------- launch ----------------
extern "C" void kernel_launch(void* const* d_in, const int* in_sizes, int n_in,
                              void* d_out, int out_size)
{
    const float* app   = (const float*)d_in[0];
    const float* edges = (const float*)d_in[1];
    const float* We    = (const float*)d_in[2];
    const float* be    = (const float*)d_in[3];
    const float* Wq    = (const float*)d_in[4];
    const float* bq    = (const float*)d_in[5];
    const float* Wk    = (const float*)d_in[6];
    // d_in[7] = bk: per-row constant in S -> cancels in softmax
    const float* Wv    = (const float*)d_in[8];
    const float* bv    = (const float*)d_in[9];
    const float* Wo    = (const float*)d_in[10];
    const float* bo    = (const float*)d_in[11];
    float* out = (float*)d_out;

    float *F, *qk, *Wqk, *Gt, *bqk, *bo2, *o1, *wp, *lp;
    cudaGetSymbolAddress((void**)&F,   g_F);
    cudaGetSymbolAddress((void**)&qk,  g_qk);
    cudaGetSymbolAddress((void**)&Wqk, g_Wqk);
    cudaGetSymbolAddress((void**)&Gt,  g_Gt);
    cudaGetSymbolAddress((void**)&bqk, g_bqk);
    cudaGetSymbolAddress((void**)&bo2, g_bo2);
    cudaGetSymbolAddress((void**)&o1,  g_o1);
    cudaGetSymbolAddress((void**)&wp,  g_wp);
    cudaGetSymbolAddress((void**)&lp,  g_lp);

    // A: weights-only (Wqk, Gt, bo2, bqk)
    preA_k<<<130, 256>>>(Wq, Wk, Wo, Wv, bq, bv, bo, Wqk, Gt, bo2, bqk);
    // B: all app-contractions (F, qk, out1)
    preB_k<<<384, 256>>>(app, We + 6, Wqk, Wo, be, bqk, F, qk, o1);
    // fused: E-build + scores + exp + aggregation (unnormalized partials)
    fused_k<<<512, 128>>>(edges, We, F, qk, wp, lp);
    // post: normalize + second-half GEMM + epilogue
    post_k<<<128, 256>>>(wp, lp, Gt, o1, bo2, out);
}

// round 12
// speedup vs baseline: 1.1192x; 1.1192x over previous
#include <cuda_runtime.h>
#include <cstddef>

typedef unsigned long long ull;

#define Nn   512
#define IND  256
#define HIDD 256
#define AH   128
#define OUTD 256
#define WELD 262   // IN_DIM + 6
#define SCALE 0.08838834764831845f

// ---------------- scratch ----------------
__device__ float g_F[Nn * HIDD];
__device__ float g_qk[Nn * HIDD];
__device__ float g_w[Nn * HIDD];
__device__ float g_Wqk[IND * HIDD];
__device__ float g_Gt[OUTD * HIDD];
__device__ float g_bqk[HIDD];
__device__ float g_bo2[OUTD];

// ---------------- f32x2 helpers ----------------
__device__ __forceinline__ ull pack2(float lo, float hi) {
    ull r; asm("mov.b64 %0,{%1,%2};" : "=l"(r) : "f"(lo), "f"(hi)); return r;
}
__device__ __forceinline__ float2 unp2(ull x) {
    float2 f; asm("mov.b64 {%0,%1},%2;" : "=f"(f.x), "=f"(f.y) : "l"(x)); return f;
}
__device__ __forceinline__ ull fma2(ull a, ull b, ull c) {
    ull d; asm("fma.rn.f32x2 %0,%1,%2,%3;" : "=l"(d) : "l"(a), "l"(b), "l"(c)); return d;
}
__device__ __forceinline__ ull relu2(ull x) {
    ull r;
    asm("{.reg .f32 lo,hi;\n\t"
        "mov.b64 {lo,hi},%1;\n\t"
        "max.f32 lo,lo,0f00000000;\n\t"
        "max.f32 hi,hi,0f00000000;\n\t"
        "mov.b64 %0,{lo,hi};}" : "=l"(r) : "l"(x));
    return r;
}

// ============ launch A: weight-only precomputes (R11-validated) =============
// bid<64 : Wqk[f,h] = SCALE * sum_a Wq[a,f]*Wk[a,h]      (K=128)
// bid<128: Gt[n,h]  = sum_d Wo[n,256+d]*Wv[d,h]          (K=256)
// bid=128: bo2 = bo + Wo2@bv ;  bid=129: bqk = SCALE*(bq@Wk)
__global__ __launch_bounds__(256) void preA_k(
    const float* __restrict__ Wq, const float* __restrict__ Wk,
    const float* __restrict__ Wo, const float* __restrict__ Wv,
    const float* __restrict__ bq, const float* __restrict__ bv,
    const float* __restrict__ bo,
    float* __restrict__ Wqk, float* __restrict__ Gt,
    float* __restrict__ bo2, float* __restrict__ bqk)
{
    const int bid = blockIdx.x;
    const int t = threadIdx.x;

    if (bid >= 128) {
        if (bid == 128) {                       // bo2
            float acc = bo[t];
            const float* arow = Wo + (size_t)t * 512 + 256;
#pragma unroll 8
            for (int d = 0; d < 256; d++) acc += bv[d] * arow[d];
            bo2[t] = acc;
        } else {                                // bqk
            float acc = 0.f;
#pragma unroll 8
            for (int a = 0; a < 128; a++) acc += bq[a] * Wk[(size_t)a * HIDD + t];
            bqk[t] = acc * SCALE;
        }
        return;
    }

    __shared__ float As[2][32][34];
    __shared__ float Bs[2][32][34];
    const int tx = t & 15, ty = t >> 4;
    const bool isW = bid < 64;
    const int x = isW ? bid : bid - 64;
    const int mb = (x >> 3) * 32, nb = (x & 7) * 32;
    const int steps = isW ? 4 : 8;

    float ra[4], rb[4];
#pragma unroll
    for (int r = 0; r < 4; r++) {
        int idx = t + r * 256;
        if (isW) {
            int kq = idx >> 5, pq = idx & 31;
            ra[r] = Wq[(size_t)kq * IND + mb + pq];
            rb[r] = Wk[(size_t)kq * HIDD + nb + pq];
        } else {
            int p = idx >> 5, s = idx & 31;
            ra[r] = Wo[(size_t)(mb + p) * 512 + 256 + s];
            rb[r] = Wv[(size_t)p * HIDD + nb + s];
        }
    }
#pragma unroll
    for (int r = 0; r < 4; r++) {
        int idx = t + r * 256;
        if (isW) {
            int kq = idx >> 5, pq = idx & 31;
            As[0][kq][pq] = ra[r];
            Bs[0][kq][pq] = rb[r];
        } else {
            int p = idx >> 5, s = idx & 31;
            As[0][s][p] = ra[r];
            Bs[0][p][s] = rb[r];
        }
    }
    __syncthreads();

    float a00 = 0.f, a01 = 0.f, a10 = 0.f, a11 = 0.f;
    for (int step = 0; step < steps; step++) {
        int cur = step & 1;
        if (step < steps - 1) {
            int k0 = (step + 1) * 32;
#pragma unroll
            for (int r = 0; r < 4; r++) {
                int idx = t + r * 256;
                if (isW) {
                    int kq = idx >> 5, pq = idx & 31;
                    ra[r] = Wq[(size_t)(k0 + kq) * IND + mb + pq];
                    rb[r] = Wk[(size_t)(k0 + kq) * HIDD + nb + pq];
                } else {
                    int p = idx >> 5, s = idx & 31;
                    ra[r] = Wo[(size_t)(mb + p) * 512 + 256 + k0 + s];
                    rb[r] = Wv[(size_t)(k0 + p) * HIDD + nb + s];
                }
            }
        }
#pragma unroll
        for (int kk = 0; kk < 32; kk++) {
            float2 av = *(const float2*)&As[cur][kk][ty * 2];
            float2 bv2 = *(const float2*)&Bs[cur][kk][tx * 2];
            a00 = fmaf(av.x, bv2.x, a00);
            a01 = fmaf(av.x, bv2.y, a01);
            a10 = fmaf(av.y, bv2.x, a10);
            a11 = fmaf(av.y, bv2.y, a11);
        }
        if (step < steps - 1) {
            __syncthreads();
            int nxt = cur ^ 1;
#pragma unroll
            for (int r = 0; r < 4; r++) {
                int idx = t + r * 256;
                if (isW) {
                    int kq = idx >> 5, pq = idx & 31;
                    As[nxt][kq][pq] = ra[r];
                    Bs[nxt][kq][pq] = rb[r];
                } else {
                    int p = idx >> 5, s = idx & 31;
                    As[nxt][s][p] = ra[r];
                    Bs[nxt][p][s] = rb[r];
                }
            }
            __syncthreads();
        }
    }

    int m = mb + ty * 2, n = nb + tx * 2;
    if (isW) {
        Wqk[(size_t)m * HIDD + n]           = a00 * SCALE;
        Wqk[(size_t)m * HIDD + n + 1]       = a01 * SCALE;
        Wqk[(size_t)(m + 1) * HIDD + n]     = a10 * SCALE;
        Wqk[(size_t)(m + 1) * HIDD + n + 1] = a11 * SCALE;
    } else {
        Gt[(size_t)m * HIDD + n]           = a00;
        Gt[(size_t)m * HIDD + n + 1]       = a01;
        Gt[(size_t)(m + 1) * HIDD + n]     = a10;
        Gt[(size_t)(m + 1) * HIDD + n + 1] = a11;
    }
}

// ============ launch B: F and qk (K=256, 256 blocks) ========================
// bid<128 : F  = app@We6^T + be
// else    : qk = app@Wqk + bqk          (Wqk pre-scaled)
__global__ __launch_bounds__(256) void preB_k(
    const float* __restrict__ app,
    const float* __restrict__ We6,
    const float* __restrict__ Wqk,
    const float* __restrict__ be,
    const float* __restrict__ bqk,
    float* __restrict__ F,
    float* __restrict__ qk)
{
    __shared__ float As[2][32][34];
    __shared__ float Bs[2][32][34];
    const int t = threadIdx.x;
    const int tx = t & 15, ty = t >> 4;
    const int bid = blockIdx.x;
    const bool isF = bid < 128;
    const int x = bid & 127;
    const int mb = (x >> 3) * 32, nb = (x & 7) * 32;

    float ra[4], rb[4];
#pragma unroll
    for (int r = 0; r < 4; r++) {
        int idx = t + r * 256, p = idx >> 5, s = idx & 31;
        ra[r] = app[(size_t)(mb + p) * IND + s];
        rb[r] = isF ? We6[(size_t)(nb + p) * WELD + s]
                    : Wqk[(size_t)p * HIDD + nb + s];
    }
#pragma unroll
    for (int r = 0; r < 4; r++) {
        int idx = t + r * 256, p = idx >> 5, s = idx & 31;
        As[0][s][p] = ra[r];
        if (isF) Bs[0][s][p] = rb[r]; else Bs[0][p][s] = rb[r];
    }
    __syncthreads();

    float a00 = 0.f, a01 = 0.f, a10 = 0.f, a11 = 0.f;
    for (int step = 0; step < 8; step++) {
        int cur = step & 1;
        if (step < 7) {
            int k0 = (step + 1) * 32;
#pragma unroll
            for (int r = 0; r < 4; r++) {
                int idx = t + r * 256, p = idx >> 5, s = idx & 31;
                ra[r] = app[(size_t)(mb + p) * IND + k0 + s];
                rb[r] = isF ? We6[(size_t)(nb + p) * WELD + k0 + s]
                            : Wqk[(size_t)(k0 + p) * HIDD + nb + s];
            }
        }
#pragma unroll
        for (int kk = 0; kk < 32; kk++) {
            float2 av = *(const float2*)&As[cur][kk][ty * 2];
            float2 bv2 = *(const float2*)&Bs[cur][kk][tx * 2];
            a00 = fmaf(av.x, bv2.x, a00);
            a01 = fmaf(av.x, bv2.y, a01);
            a10 = fmaf(av.y, bv2.x, a10);
            a11 = fmaf(av.y, bv2.y, a11);
        }
        if (step < 7) {
            __syncthreads();
            int nxt = cur ^ 1;
#pragma unroll
            for (int r = 0; r < 4; r++) {
                int idx = t + r * 256, p = idx >> 5, s = idx & 31;
                As[nxt][s][p] = ra[r];
                if (isF) Bs[nxt][s][p] = rb[r]; else Bs[nxt][p][s] = rb[r];
            }
            __syncthreads();
        }
    }

    int m = mb + ty * 2, n = nb + tx * 2;
    float* C = isF ? F : qk;
    const float* bias = isF ? be : bqk;
    float b0 = bias[n], b1 = bias[n + 1];
    C[(size_t)m * HIDD + n]           = a00 + b0;
    C[(size_t)m * HIDD + n + 1]       = a01 + b1;
    C[(size_t)(m + 1) * HIDD + n]     = a10 + b0;
    C[(size_t)(m + 1) * HIDD + n + 1] = a11 + b1;
}

// ================= fused attention middle (EXACT R8 kernel) =================
// w[i,h] = (1/l_i) * sum_j exp(s_ij) * E[i,j,h],  E = relu(F[j]+e(i,j)·We6)
// 256 threads = 8 warps. Warp w handles j = tau*8+w. Lane l owns h = 8l..8l+7.
#define FU_SMEM ((6144 + 768 + 2048) * 8 + 64)

__global__ __launch_bounds__(256, 2) void fused_k(
    const float* __restrict__ edges,
    const float* __restrict__ We,
    const float* __restrict__ Fm,
    const float* __restrict__ qkm,
    float* __restrict__ wout)
{
    extern __shared__ __align__(16) ull smf[];
    ull*   e2    = smf;                 // [2][512][6] dup-packed edges (48KB)
    ull*   We2s  = e2 + 6144;           // [128 hp][6] pair-packed (6KB)
    ull*   waccs = We2s + 768;          // [8 w][32 l][8 slot] (16KB)
    float* wl    = (float*)(waccs + 2048);  // [8 w][2 i]

    const int t = threadIdx.x;
    const int l = t & 31, w = t >> 5;
    const int ib = blockIdx.x * 2;

    {
        const float* esrc = edges + (size_t)ib * (Nn * 6);
        for (int idx = t; idx < 2 * Nn * 6; idx += 256) {
            float v = esrc[idx];
            e2[idx] = pack2(v, v);
        }
    }
    for (int idx = t; idx < 128 * 6; idx += 256) {
        int hp = idx / 6, c = idx - hp * 6;
        We2s[idx] = pack2(We[(size_t)(2 * hp) * WELD + c],
                          We[(size_t)(2 * hp + 1) * WELD + c]);
    }
    __syncthreads();

    ull W2[4][6];
#pragma unroll
    for (int k = 0; k < 4; k++) {
        int hp = 4 * l + k;
#pragma unroll
        for (int c = 0; c < 6; c++) W2[k][c] = We2s[hp * 6 + c];
    }
    ull qk2[2][4];
    {
        const ulonglong2* qa =
            (const ulonglong2*)(qkm + (size_t)ib * HIDD + 8 * l);
        const ulonglong2* qb =
            (const ulonglong2*)(qkm + (size_t)(ib + 1) * HIDD + 8 * l);
        ulonglong2 v0 = qa[0], v1 = qa[1];
        qk2[0][0] = v0.x; qk2[0][1] = v0.y; qk2[0][2] = v1.x; qk2[0][3] = v1.y;
        v0 = qb[0]; v1 = qb[1];
        qk2[1][0] = v0.x; qk2[1][1] = v0.y; qk2[1][2] = v1.x; qk2[1][3] = v1.y;
    }

    ull z = pack2(0.f, 0.f);
    ull acc[2][4] = {{z, z, z, z}, {z, z, z, z}};
    float lw0 = 0.f, lw1 = 0.f;

    ull Fc[4], Fn[4];
    {
        const ulonglong2* fp = (const ulonglong2*)(Fm + (size_t)w * HIDD + 8 * l);
        ulonglong2 v0 = fp[0], v1 = fp[1];
        Fc[0] = v0.x; Fc[1] = v0.y; Fc[2] = v1.x; Fc[3] = v1.y;
    }

    for (int tau = 0; tau < 64; tau++) {
        const int jj = tau * 8 + w;
        if (tau < 63) {
            const ulonglong2* fp =
                (const ulonglong2*)(Fm + (size_t)(jj + 8) * HIDD + 8 * l);
            ulonglong2 v0 = fp[0], v1 = fp[1];
            Fn[0] = v0.x; Fn[1] = v0.y; Fn[2] = v1.x; Fn[3] = v1.y;
        }
#pragma unroll
        for (int i = 0; i < 2; i++) {
            const ull* ep = e2 + (i * Nn + jj) * 6;        // broadcast reads
            ull e0 = ep[0], e1 = ep[1], e2v = ep[2];
            ull e3 = ep[3], e4 = ep[4], e5 = ep[5];
            ull g[4];
#pragma unroll
            for (int k = 0; k < 4; k++) {
                ull gg = fma2(e0, W2[k][0], Fc[k]);
                gg = fma2(e1, W2[k][1], gg);
                gg = fma2(e2v, W2[k][2], gg);
                gg = fma2(e3, W2[k][3], gg);
                gg = fma2(e4, W2[k][4], gg);
                gg = fma2(e5, W2[k][5], gg);
                g[k] = relu2(gg);
            }
            ull sd = fma2(qk2[i][0], g[0], z);
            sd = fma2(qk2[i][1], g[1], sd);
            sd = fma2(qk2[i][2], g[2], sd);
            sd = fma2(qk2[i][3], g[3], sd);
            float2 sv = unp2(sd);
            float s = sv.x + sv.y;
#pragma unroll
            for (int o = 16; o; o >>= 1)
                s += __shfl_xor_sync(0xffffffffu, s, o);
            float p = (jj == ib + i) ? 0.f : __expf(s);
            if (i == 0) lw0 += p; else lw1 += p;
            ull p2 = pack2(p, p);
#pragma unroll
            for (int k = 0; k < 4; k++)
                acc[i][k] = fma2(p2, g[k], acc[i][k]);
        }
#pragma unroll
        for (int k = 0; k < 4; k++) Fc[k] = Fn[k];
    }

    ull* wb = waccs + (w * 32 + l) * 8;
#pragma unroll
    for (int k = 0; k < 4; k++) { wb[k] = acc[0][k]; wb[4 + k] = acc[1][k]; }
    if (l == 0) { wl[w * 2] = lw0; wl[w * 2 + 1] = lw1; }
    __syncthreads();
    {
        int i = t >> 7, hp = t & 127;
        int lo = hp >> 2, ko = hp & 3;
        float sx = 0.f, sy = 0.f, li = 0.f;
#pragma unroll
        for (int ww = 0; ww < 8; ww++) {
            float2 v = unp2(waccs[(ww * 32 + lo) * 8 + i * 4 + ko]);
            sx += v.x; sy += v.y;
            li += wl[ww * 2 + i];
        }
        float inv = 1.f / li;
        *(float2*)(wout + (size_t)(ib + i) * HIDD + 2 * hp) =
            make_float2(sx * inv, sy * inv);
    }
}

// ============ post: out = relu([app|w] @ [Wo1;Gt]^T + bo2), K=512 ===========
// (EXACT R10 kernel — measured 15.7us in a passing run)
__global__ __launch_bounds__(256) void post_k(
    const float* __restrict__ app,
    const float* __restrict__ w,
    const float* __restrict__ Wo,
    const float* __restrict__ Gt,
    const float* __restrict__ bo2,
    float* __restrict__ out)
{
    __shared__ float As[2][32][34];
    __shared__ float Bs[2][32][34];
    const int t = threadIdx.x;
    const int tx = t & 15, ty = t >> 4;
    const int mb = (blockIdx.x >> 3) * 32, nb = (blockIdx.x & 7) * 32;

    float ra[4], rb[4];
#pragma unroll
    for (int r = 0; r < 4; r++) {
        int idx = t + r * 256, p = idx >> 5, s = idx & 31;
        ra[r] = app[(size_t)(mb + p) * IND + s];
        rb[r] = Wo[(size_t)(nb + p) * 512 + s];
    }
#pragma unroll
    for (int r = 0; r < 4; r++) {
        int idx = t + r * 256, p = idx >> 5, s = idx & 31;
        As[0][s][p] = ra[r];
        Bs[0][s][p] = rb[r];
    }
    __syncthreads();

    float a00 = 0.f, a01 = 0.f, a10 = 0.f, a11 = 0.f;
    for (int step = 0; step < 16; step++) {      // K = 512
        int cur = step & 1;
        if (step < 15) {
            int k0 = (step + 1) * 32;
#pragma unroll
            for (int r = 0; r < 4; r++) {
                int idx = t + r * 256, p = idx >> 5, s = idx & 31;
                if (k0 < 256) {
                    ra[r] = app[(size_t)(mb + p) * IND + k0 + s];
                    rb[r] = Wo[(size_t)(nb + p) * 512 + k0 + s];
                } else {
                    ra[r] = w[(size_t)(mb + p) * HIDD + (k0 - 256) + s];
                    rb[r] = Gt[(size_t)(nb + p) * HIDD + (k0 - 256) + s];
                }
            }
        }
#pragma unroll
        for (int kk = 0; kk < 32; kk++) {
            float2 av = *(const float2*)&As[cur][kk][ty * 2];
            float2 bv2 = *(const float2*)&Bs[cur][kk][tx * 2];
            a00 = fmaf(av.x, bv2.x, a00);
            a01 = fmaf(av.x, bv2.y, a01);
            a10 = fmaf(av.y, bv2.x, a10);
            a11 = fmaf(av.y, bv2.y, a11);
        }
        if (step < 15) {
            __syncthreads();
            int nxt = cur ^ 1;
#pragma unroll
            for (int r = 0; r < 4; r++) {
                int idx = t + r * 256, p = idx >> 5, s = idx & 31;
                As[nxt][s][p] = ra[r];
                Bs[nxt][s][p] = rb[r];
            }
            __syncthreads();
        }
    }

    int m = mb + ty * 2, n = nb + tx * 2;
    float b0 = bo2[n], b1 = bo2[n + 1];
    out[(size_t)m * OUTD + n]           = fmaxf(a00 + b0, 0.f);
    out[(size_t)m * OUTD + n + 1]       = fmaxf(a01 + b1, 0.f);
    out[(size_t)(m + 1) * OUTD + n]     = fmaxf(a10 + b0, 0.f);
    out[(size_t)(m + 1) * OUTD + n + 1] = fmaxf(a11 + b1, 0.f);
}

// ---------------- launch ----------------
extern "C" void kernel_launch(void* const* d_in, const int* in_sizes, int n_in,
                              void* d_out, int out_size)
{
    const float* app   = (const float*)d_in[0];
    const float* edges = (const float*)d_in[1];
    const float* We    = (const float*)d_in[2];
    const float* be    = (const float*)d_in[3];
    const float* Wq    = (const float*)d_in[4];
    const float* bq    = (const float*)d_in[5];
    const float* Wk    = (const float*)d_in[6];
    // d_in[7] = bk: per-row constant in S -> cancels in softmax
    const float* Wv    = (const float*)d_in[8];
    const float* bv    = (const float*)d_in[9];
    const float* Wo    = (const float*)d_in[10];
    const float* bo    = (const float*)d_in[11];
    float* out = (float*)d_out;

    float *F, *qk, *w, *Wqk, *Gt, *bqk, *bo2;
    cudaGetSymbolAddress((void**)&F,   g_F);
    cudaGetSymbolAddress((void**)&qk,  g_qk);
    cudaGetSymbolAddress((void**)&w,   g_w);
    cudaGetSymbolAddress((void**)&Wqk, g_Wqk);
    cudaGetSymbolAddress((void**)&Gt,  g_Gt);
    cudaGetSymbolAddress((void**)&bqk, g_bqk);
    cudaGetSymbolAddress((void**)&bo2, g_bo2);

    cudaFuncSetAttribute(fused_k, cudaFuncAttributeMaxDynamicSharedMemorySize,
                         FU_SMEM);

    // A: weights-only (Wqk, Gt, bo2, bqk)
    preA_k<<<130, 256>>>(Wq, Wk, Wo, Wv, bq, bv, bo, Wqk, Gt, bo2, bqk);
    // B: F and qk
    preB_k<<<256, 256>>>(app, We + 6, Wqk, be, bqk, F, qk);
    // fused (R8): E-build + scores + softmax + aggregation -> normalized w
    fused_k<<<Nn / 2, 256, FU_SMEM>>>(edges, We, F, qk, w);
    // post (R10): out = relu([app|w] @ [Wo1;Gt]^T + bo2)
    post_k<<<128, 256>>>(app, w, Wo, Gt, bo2, out);
}

// round 13
// speedup vs baseline: 1.4179x; 1.2668x over previous
#include <cuda_runtime.h>
#include <cstddef>

typedef unsigned long long ull;

#define Nn   512
#define IND  256
#define HIDD 256
#define AH   128
#define OUTD 256
#define WELD 262   // IN_DIM + 6
#define SCALE 0.08838834764831845f

// ---------------- scratch ----------------
__device__ float g_F[Nn * HIDD];
__device__ float g_qk[Nn * HIDD];
__device__ float g_w[Nn * HIDD];
__device__ float g_Wqk[IND * HIDD];
__device__ float g_Gt[OUTD * HIDD];
__device__ float g_bqk[HIDD];
__device__ float g_bo2[OUTD];

// ---------------- f32x2 helpers ----------------
__device__ __forceinline__ ull pack2(float lo, float hi) {
    ull r; asm("mov.b64 %0,{%1,%2};" : "=l"(r) : "f"(lo), "f"(hi)); return r;
}
__device__ __forceinline__ float2 unp2(ull x) {
    float2 f; asm("mov.b64 {%0,%1},%2;" : "=f"(f.x), "=f"(f.y) : "l"(x)); return f;
}
__device__ __forceinline__ ull fma2(ull a, ull b, ull c) {
    ull d; asm("fma.rn.f32x2 %0,%1,%2,%3;" : "=l"(d) : "l"(a), "l"(b), "l"(c)); return d;
}
__device__ __forceinline__ ull relu2(ull x) {
    ull r;
    asm("{.reg .f32 lo,hi;\n\t"
        "mov.b64 {lo,hi},%1;\n\t"
        "max.f32 lo,lo,0f00000000;\n\t"
        "max.f32 hi,hi,0f00000000;\n\t"
        "mov.b64 %0,{lo,hi};}" : "=l"(r) : "l"(x));
    return r;
}

// ============ launch A: weight-only precomputes =============================
// bid<64 : Wqk[f,h] = SCALE * sum_a Wq[a,f]*Wk[a,h]      (K=128)
// bid<128: Gt[n,h]  = sum_d Wo[n,256+d]*Wv[d,h]          (K=256)
// bid=128: bo2 = bo + Wo2@bv  (COALESCED warp-per-row)
// bid=129: bqk = SCALE*(bq@Wk)
__global__ __launch_bounds__(256) void preA_k(
    const float* __restrict__ Wq, const float* __restrict__ Wk,
    const float* __restrict__ Wo, const float* __restrict__ Wv,
    const float* __restrict__ bq, const float* __restrict__ bv,
    const float* __restrict__ bo,
    float* __restrict__ Wqk, float* __restrict__ Gt,
    float* __restrict__ bo2, float* __restrict__ bqk)
{
    const int bid = blockIdx.x;
    const int t = threadIdx.x;

    if (bid >= 128) {
        if (bid == 128) {
            // bo2[n] = bo[n] + sum_d Wo[n,256+d]*bv[d], warp-per-row coalesced
            const int l = t & 31, w = t >> 5;
            for (int n = w; n < OUTD; n += 8) {
                const float* arow = Wo + (size_t)n * 512 + 256;
                float acc = 0.f;
#pragma unroll
                for (int k = 0; k < 8; k++)
                    acc += bv[l + 32 * k] * arow[l + 32 * k];
#pragma unroll
                for (int o = 16; o; o >>= 1)
                    acc += __shfl_xor_sync(0xffffffffu, acc, o);
                if (l == 0) bo2[n] = acc + bo[n];
            }
        } else {                                // bqk (coalesced over t)
            float acc = 0.f;
#pragma unroll 8
            for (int a = 0; a < 128; a++) acc += bq[a] * Wk[(size_t)a * HIDD + t];
            bqk[t] = acc * SCALE;
        }
        return;
    }

    __shared__ float As[2][32][34];
    __shared__ float Bs[2][32][34];
    const int tx = t & 15, ty = t >> 4;
    const bool isW = bid < 64;
    const int x = isW ? bid : bid - 64;
    const int mb = (x >> 3) * 32, nb = (x & 7) * 32;
    const int steps = isW ? 4 : 8;

    float ra[4], rb[4];
#pragma unroll
    for (int r = 0; r < 4; r++) {
        int idx = t + r * 256;
        if (isW) {
            int kq = idx >> 5, pq = idx & 31;
            ra[r] = Wq[(size_t)kq * IND + mb + pq];
            rb[r] = Wk[(size_t)kq * HIDD + nb + pq];
        } else {
            int p = idx >> 5, s = idx & 31;
            ra[r] = Wo[(size_t)(mb + p) * 512 + 256 + s];
            rb[r] = Wv[(size_t)p * HIDD + nb + s];
        }
    }
#pragma unroll
    for (int r = 0; r < 4; r++) {
        int idx = t + r * 256;
        if (isW) {
            int kq = idx >> 5, pq = idx & 31;
            As[0][kq][pq] = ra[r];
            Bs[0][kq][pq] = rb[r];
        } else {
            int p = idx >> 5, s = idx & 31;
            As[0][s][p] = ra[r];
            Bs[0][p][s] = rb[r];
        }
    }
    __syncthreads();

    float a00 = 0.f, a01 = 0.f, a10 = 0.f, a11 = 0.f;
    for (int step = 0; step < steps; step++) {
        int cur = step & 1;
        if (step < steps - 1) {
            int k0 = (step + 1) * 32;
#pragma unroll
            for (int r = 0; r < 4; r++) {
                int idx = t + r * 256;
                if (isW) {
                    int kq = idx >> 5, pq = idx & 31;
                    ra[r] = Wq[(size_t)(k0 + kq) * IND + mb + pq];
                    rb[r] = Wk[(size_t)(k0 + kq) * HIDD + nb + pq];
                } else {
                    int p = idx >> 5, s = idx & 31;
                    ra[r] = Wo[(size_t)(mb + p) * 512 + 256 + k0 + s];
                    rb[r] = Wv[(size_t)(k0 + p) * HIDD + nb + s];
                }
            }
        }
#pragma unroll
        for (int kk = 0; kk < 32; kk++) {
            float2 av = *(const float2*)&As[cur][kk][ty * 2];
            float2 bv2 = *(const float2*)&Bs[cur][kk][tx * 2];
            a00 = fmaf(av.x, bv2.x, a00);
            a01 = fmaf(av.x, bv2.y, a01);
            a10 = fmaf(av.y, bv2.x, a10);
            a11 = fmaf(av.y, bv2.y, a11);
        }
        if (step < steps - 1) {
            __syncthreads();
            int nxt = cur ^ 1;
#pragma unroll
            for (int r = 0; r < 4; r++) {
                int idx = t + r * 256;
                if (isW) {
                    int kq = idx >> 5, pq = idx & 31;
                    As[nxt][kq][pq] = ra[r];
                    Bs[nxt][kq][pq] = rb[r];
                } else {
                    int p = idx >> 5, s = idx & 31;
                    As[nxt][s][p] = ra[r];
                    Bs[nxt][p][s] = rb[r];
                }
            }
            __syncthreads();
        }
    }

    int m = mb + ty * 2, n = nb + tx * 2;
    if (isW) {
        Wqk[(size_t)m * HIDD + n]           = a00 * SCALE;
        Wqk[(size_t)m * HIDD + n + 1]       = a01 * SCALE;
        Wqk[(size_t)(m + 1) * HIDD + n]     = a10 * SCALE;
        Wqk[(size_t)(m + 1) * HIDD + n + 1] = a11 * SCALE;
    } else {
        Gt[(size_t)m * HIDD + n]           = a00;
        Gt[(size_t)m * HIDD + n + 1]       = a01;
        Gt[(size_t)(m + 1) * HIDD + n]     = a10;
        Gt[(size_t)(m + 1) * HIDD + n + 1] = a11;
    }
}

// ============ launch B: F and qk (K=256, 256 blocks) ========================
__global__ __launch_bounds__(256) void preB_k(
    const float* __restrict__ app,
    const float* __restrict__ We6,
    const float* __restrict__ Wqk,
    const float* __restrict__ be,
    const float* __restrict__ bqk,
    float* __restrict__ F,
    float* __restrict__ qk)
{
    __shared__ float As[2][32][34];
    __shared__ float Bs[2][32][34];
    const int t = threadIdx.x;
    const int tx = t & 15, ty = t >> 4;
    const int bid = blockIdx.x;
    const bool isF = bid < 128;
    const int x = bid & 127;
    const int mb = (x >> 3) * 32, nb = (x & 7) * 32;

    float ra[4], rb[4];
#pragma unroll
    for (int r = 0; r < 4; r++) {
        int idx = t + r * 256, p = idx >> 5, s = idx & 31;
        ra[r] = app[(size_t)(mb + p) * IND + s];
        rb[r] = isF ? We6[(size_t)(nb + p) * WELD + s]
                    : Wqk[(size_t)p * HIDD + nb + s];
    }
#pragma unroll
    for (int r = 0; r < 4; r++) {
        int idx = t + r * 256, p = idx >> 5, s = idx & 31;
        As[0][s][p] = ra[r];
        if (isF) Bs[0][s][p] = rb[r]; else Bs[0][p][s] = rb[r];
    }
    __syncthreads();

    float a00 = 0.f, a01 = 0.f, a10 = 0.f, a11 = 0.f;
    for (int step = 0; step < 8; step++) {
        int cur = step & 1;
        if (step < 7) {
            int k0 = (step + 1) * 32;
#pragma unroll
            for (int r = 0; r < 4; r++) {
                int idx = t + r * 256, p = idx >> 5, s = idx & 31;
                ra[r] = app[(size_t)(mb + p) * IND + k0 + s];
                rb[r] = isF ? We6[(size_t)(nb + p) * WELD + k0 + s]
                            : Wqk[(size_t)(k0 + p) * HIDD + nb + s];
            }
        }
#pragma unroll
        for (int kk = 0; kk < 32; kk++) {
            float2 av = *(const float2*)&As[cur][kk][ty * 2];
            float2 bv2 = *(const float2*)&Bs[cur][kk][tx * 2];
            a00 = fmaf(av.x, bv2.x, a00);
            a01 = fmaf(av.x, bv2.y, a01);
            a10 = fmaf(av.y, bv2.x, a10);
            a11 = fmaf(av.y, bv2.y, a11);
        }
        if (step < 7) {
            __syncthreads();
            int nxt = cur ^ 1;
#pragma unroll
            for (int r = 0; r < 4; r++) {
                int idx = t + r * 256, p = idx >> 5, s = idx & 31;
                As[nxt][s][p] = ra[r];
                if (isF) Bs[nxt][s][p] = rb[r]; else Bs[nxt][p][s] = rb[r];
            }
            __syncthreads();
        }
    }

    int m = mb + ty * 2, n = nb + tx * 2;
    float* C = isF ? F : qk;
    const float* bias = isF ? be : bqk;
    float b0 = bias[n], b1 = bias[n + 1];
    C[(size_t)m * HIDD + n]           = a00 + b0;
    C[(size_t)m * HIDD + n + 1]       = a01 + b1;
    C[(size_t)(m + 1) * HIDD + n]     = a10 + b0;
    C[(size_t)(m + 1) * HIDD + n + 1] = a11 + b1;
}

// ================= fused attention middle (EXACT R8 kernel) =================
#define FU_SMEM ((6144 + 768 + 2048) * 8 + 64)

__global__ __launch_bounds__(256, 2) void fused_k(
    const float* __restrict__ edges,
    const float* __restrict__ We,
    const float* __restrict__ Fm,
    const float* __restrict__ qkm,
    float* __restrict__ wout)
{
    extern __shared__ __align__(16) ull smf[];
    ull*   e2    = smf;                 // [2][512][6] dup-packed edges (48KB)
    ull*   We2s  = e2 + 6144;           // [128 hp][6] pair-packed (6KB)
    ull*   waccs = We2s + 768;          // [8 w][32 l][8 slot] (16KB)
    float* wl    = (float*)(waccs + 2048);  // [8 w][2 i]

    const int t = threadIdx.x;
    const int l = t & 31, w = t >> 5;
    const int ib = blockIdx.x * 2;

    {
        const float* esrc = edges + (size_t)ib * (Nn * 6);
        for (int idx = t; idx < 2 * Nn * 6; idx += 256) {
            float v = esrc[idx];
            e2[idx] = pack2(v, v);
        }
    }
    for (int idx = t; idx < 128 * 6; idx += 256) {
        int hp = idx / 6, c = idx - hp * 6;
        We2s[idx] = pack2(We[(size_t)(2 * hp) * WELD + c],
                          We[(size_t)(2 * hp + 1) * WELD + c]);
    }
    __syncthreads();

    ull W2[4][6];
#pragma unroll
    for (int k = 0; k < 4; k++) {
        int hp = 4 * l + k;
#pragma unroll
        for (int c = 0; c < 6; c++) W2[k][c] = We2s[hp * 6 + c];
    }
    ull qk2[2][4];
    {
        const ulonglong2* qa =
            (const ulonglong2*)(qkm + (size_t)ib * HIDD + 8 * l);
        const ulonglong2* qb =
            (const ulonglong2*)(qkm + (size_t)(ib + 1) * HIDD + 8 * l);
        ulonglong2 v0 = qa[0], v1 = qa[1];
        qk2[0][0] = v0.x; qk2[0][1] = v0.y; qk2[0][2] = v1.x; qk2[0][3] = v1.y;
        v0 = qb[0]; v1 = qb[1];
        qk2[1][0] = v0.x; qk2[1][1] = v0.y; qk2[1][2] = v1.x; qk2[1][3] = v1.y;
    }

    ull z = pack2(0.f, 0.f);
    ull acc[2][4] = {{z, z, z, z}, {z, z, z, z}};
    float lw0 = 0.f, lw1 = 0.f;

    ull Fc[4], Fn[4];
    {
        const ulonglong2* fp = (const ulonglong2*)(Fm + (size_t)w * HIDD + 8 * l);
        ulonglong2 v0 = fp[0], v1 = fp[1];
        Fc[0] = v0.x; Fc[1] = v0.y; Fc[2] = v1.x; Fc[3] = v1.y;
    }

    for (int tau = 0; tau < 64; tau++) {
        const int jj = tau * 8 + w;
        if (tau < 63) {
            const ulonglong2* fp =
                (const ulonglong2*)(Fm + (size_t)(jj + 8) * HIDD + 8 * l);
            ulonglong2 v0 = fp[0], v1 = fp[1];
            Fn[0] = v0.x; Fn[1] = v0.y; Fn[2] = v1.x; Fn[3] = v1.y;
        }
#pragma unroll
        for (int i = 0; i < 2; i++) {
            const ull* ep = e2 + (i * Nn + jj) * 6;        // broadcast reads
            ull e0 = ep[0], e1 = ep[1], e2v = ep[2];
            ull e3 = ep[3], e4 = ep[4], e5 = ep[5];
            ull g[4];
#pragma unroll
            for (int k = 0; k < 4; k++) {
                ull gg = fma2(e0, W2[k][0], Fc[k]);
                gg = fma2(e1, W2[k][1], gg);
                gg = fma2(e2v, W2[k][2], gg);
                gg = fma2(e3, W2[k][3], gg);
                gg = fma2(e4, W2[k][4], gg);
                gg = fma2(e5, W2[k][5], gg);
                g[k] = relu2(gg);
            }
            ull sd = fma2(qk2[i][0], g[0], z);
            sd = fma2(qk2[i][1], g[1], sd);
            sd = fma2(qk2[i][2], g[2], sd);
            sd = fma2(qk2[i][3], g[3], sd);
            float2 sv = unp2(sd);
            float s = sv.x + sv.y;
#pragma unroll
            for (int o = 16; o; o >>= 1)
                s += __shfl_xor_sync(0xffffffffu, s, o);
            float p = (jj == ib + i) ? 0.f : __expf(s);
            if (i == 0) lw0 += p; else lw1 += p;
            ull p2 = pack2(p, p);
#pragma unroll
            for (int k = 0; k < 4; k++)
                acc[i][k] = fma2(p2, g[k], acc[i][k]);
        }
#pragma unroll
        for (int k = 0; k < 4; k++) Fc[k] = Fn[k];
    }

    ull* wb = waccs + (w * 32 + l) * 8;
#pragma unroll
    for (int k = 0; k < 4; k++) { wb[k] = acc[0][k]; wb[4 + k] = acc[1][k]; }
    if (l == 0) { wl[w * 2] = lw0; wl[w * 2 + 1] = lw1; }
    __syncthreads();
    {
        int i = t >> 7, hp = t & 127;
        int lo = hp >> 2, ko = hp & 3;
        float sx = 0.f, sy = 0.f, li = 0.f;
#pragma unroll
        for (int ww = 0; ww < 8; ww++) {
            float2 v = unp2(waccs[(ww * 32 + lo) * 8 + i * 4 + ko]);
            sx += v.x; sy += v.y;
            li += wl[ww * 2 + i];
        }
        float inv = 1.f / li;
        *(float2*)(wout + (size_t)(ib + i) * HIDD + 2 * hp) =
            make_float2(sx * inv, sy * inv);
    }
}

// ============ post: out = relu([app|w] @ [Wo1;Gt]^T + bo2), K=512 ===========
__global__ __launch_bounds__(256) void post_k(
    const float* __restrict__ app,
    const float* __restrict__ w,
    const float* __restrict__ Wo,
    const float* __restrict__ Gt,
    const float* __restrict__ bo2,
    float* __restrict__ out)
{
    __shared__ float As[2][32][34];
    __shared__ float Bs[2][32][34];
    const int t = threadIdx.x;
    const int tx = t & 15, ty = t >> 4;
    const int mb = (blockIdx.x >> 3) * 32, nb = (blockIdx.x & 7) * 32;

    float ra[4], rb[4];
#pragma unroll
    for (int r = 0; r < 4; r++) {
        int idx = t + r * 256, p = idx >> 5, s = idx & 31;
        ra[r] = app[(size_t)(mb + p) * IND + s];
        rb[r] = Wo[(size_t)(nb + p) * 512 + s];
    }
#pragma unroll
    for (int r = 0; r < 4; r++) {
        int idx = t + r * 256, p = idx >> 5, s = idx & 31;
        As[0][s][p] = ra[r];
        Bs[0][s][p] = rb[r];
    }
    __syncthreads();

    float a00 = 0.f, a01 = 0.f, a10 = 0.f, a11 = 0.f;
    for (int step = 0; step < 16; step++) {      // K = 512
        int cur = step & 1;
        if (step < 15) {
            int k0 = (step + 1) * 32;
#pragma unroll
            for (int r = 0; r < 4; r++) {
                int idx = t + r * 256, p = idx >> 5, s = idx & 31;
                if (k0 < 256) {
                    ra[r] = app[(size_t)(mb + p) * IND + k0 + s];
                    rb[r] = Wo[(size_t)(nb + p) * 512 + k0 + s];
                } else {
                    ra[r] = w[(size_t)(mb + p) * HIDD + (k0 - 256) + s];
                    rb[r] = Gt[(size_t)(nb + p) * HIDD + (k0 - 256) + s];
                }
            }
        }
#pragma unroll
        for (int kk = 0; kk < 32; kk++) {
            float2 av = *(const float2*)&As[cur][kk][ty * 2];
            float2 bv2 = *(const float2*)&Bs[cur][kk][tx * 2];
            a00 = fmaf(av.x, bv2.x, a00);
            a01 = fmaf(av.x, bv2.y, a01);
            a10 = fmaf(av.y, bv2.x, a10);
            a11 = fmaf(av.y, bv2.y, a11);
        }
        if (step < 15) {
            __syncthreads();
            int nxt = cur ^ 1;
#pragma unroll
            for (int r = 0; r < 4; r++) {
                int idx = t + r * 256, p = idx >> 5, s = idx & 31;
                As[nxt][s][p] = ra[r];
                Bs[nxt][s][p] = rb[r];
            }
            __syncthreads();
        }
    }

    int m = mb + ty * 2, n = nb + tx * 2;
    float b0 = bo2[n], b1 = bo2[n + 1];
    out[(size_t)m * OUTD + n]           = fmaxf(a00 + b0, 0.f);
    out[(size_t)m * OUTD + n + 1]       = fmaxf(a01 + b1, 0.f);
    out[(size_t)(m + 1) * OUTD + n]     = fmaxf(a10 + b0, 0.f);
    out[(size_t)(m + 1) * OUTD + n + 1] = fmaxf(a11 + b1, 0.f);
}

// ---------------- launch ----------------
extern "C" void kernel_launch(void* const* d_in, const int* in_sizes, int n_in,
                              void* d_out, int out_size)
{
    const float* app   = (const float*)d_in[0];
    const float* edges = (const float*)d_in[1];
    const float* We    = (const float*)d_in[2];
    const float* be    = (const float*)d_in[3];
    const float* Wq    = (const float*)d_in[4];
    const float* bq    = (const float*)d_in[5];
    const float* Wk    = (const float*)d_in[6];
    // d_in[7] = bk: per-row constant in S -> cancels in softmax
    const float* Wv    = (const float*)d_in[8];
    const float* bv    = (const float*)d_in[9];
    const float* Wo    = (const float*)d_in[10];
    const float* bo    = (const float*)d_in[11];
    float* out = (float*)d_out;

    float *F, *qk, *w, *Wqk, *Gt, *bqk, *bo2;
    cudaGetSymbolAddress((void**)&F,   g_F);
    cudaGetSymbolAddress((void**)&qk,  g_qk);
    cudaGetSymbolAddress((void**)&w,   g_w);
    cudaGetSymbolAddress((void**)&Wqk, g_Wqk);
    cudaGetSymbolAddress((void**)&Gt,  g_Gt);
    cudaGetSymbolAddress((void**)&bqk, g_bqk);
    cudaGetSymbolAddress((void**)&bo2, g_bo2);

    cudaFuncSetAttribute(fused_k, cudaFuncAttributeMaxDynamicSharedMemorySize,
                         FU_SMEM);

    // A: weights-only (Wqk, Gt, bo2, bqk)
    preA_k<<<130, 256>>>(Wq, Wk, Wo, Wv, bq, bv, bo, Wqk, Gt, bo2, bqk);
    // B: F and qk
    preB_k<<<256, 256>>>(app, We + 6, Wqk, be, bqk, F, qk);
    // fused (R8): E-build + scores + softmax + aggregation -> normalized w
    fused_k<<<Nn / 2, 256, FU_SMEM>>>(edges, We, F, qk, w);
    // post (R10): out = relu([app|w] @ [Wo1;Gt]^T + bo2)
    post_k<<<128, 256>>>(app, w, Wo, Gt, bo2, out);
}